// round 17
// baseline (speedup 1.0000x reference)
#include <cuda_runtime.h>
#include <cuda_fp16.h>
#include <cstdint>

// Problem constants
#define S_LEN    2048
#define DMODEL   1024
#define NHEADS   16
#define DK       64
#define BATCH    2
#define M_TOTAL  (BATCH * S_LEN)   // 4096

// Scratch (allocation-free rule: __device__ globals)
__device__ __half g_q[BATCH * NHEADS * S_LEN * DK];    // (B,H,S,dk) fp16, pre-scaled
__device__ __half g_k[BATCH * NHEADS * S_LEN * DK];
__device__ __half g_v[BATCH * NHEADS * S_LEN * DK];
__device__ __half g_att[BATCH * S_LEN * DMODEL];       // (B,S,D) fp16
__device__ __half g_half[8 * 1024 * 1024];             // fp16 x + 4 weights

// Q pre-scale folded into QKV epilogue: (1/sqrt(dk)) * log2(e)
#define QSCALE 0.1803368801f

// ---------------------------------------------------------------------------
// Helpers
// ---------------------------------------------------------------------------
__device__ __forceinline__ uint32_t smem_u32(const void* p) {
    uint32_t a;
    asm("{ .reg .u64 t; cvta.to.shared.u64 t, %1; cvt.u32.u64 %0, t; }"
        : "=r"(a) : "l"(p));
    return a;
}

__device__ __forceinline__ void cp_async16(uint32_t s, const void* g) {
    asm volatile("cp.async.cg.shared.global [%0], [%1], 16;" :: "r"(s), "l"(g));
}
#define CP_COMMIT() asm volatile("cp.async.commit_group;" ::: "memory")
#define CP_WAIT(n)  asm volatile("cp.async.wait_group %0;" :: "n"(n) : "memory")

// D(16x8) += A(16x16,row) * B(16x8,col) -- fp16 operands, fp32 accum
__device__ __forceinline__ void mma_f16(float* d,
                                        uint32_t a0, uint32_t a1, uint32_t a2, uint32_t a3,
                                        uint32_t b0, uint32_t b1) {
    asm volatile(
        "mma.sync.aligned.m16n8k16.row.col.f32.f16.f16.f32 "
        "{%0,%1,%2,%3}, {%4,%5,%6,%7}, {%8,%9}, {%0,%1,%2,%3};"
        : "+f"(d[0]), "+f"(d[1]), "+f"(d[2]), "+f"(d[3])
        : "r"(a0), "r"(a1), "r"(a2), "r"(a3), "r"(b0), "r"(b1));
}

__device__ __forceinline__ void ldsm4(uint32_t* r, uint32_t addr) {
    asm volatile("ldmatrix.sync.aligned.m8n8.x4.shared.b16 {%0,%1,%2,%3}, [%4];"
        : "=r"(r[0]), "=r"(r[1]), "=r"(r[2]), "=r"(r[3]) : "r"(addr));
}

__device__ __forceinline__ void ldsm4t(uint32_t* r, uint32_t addr) {
    asm volatile("ldmatrix.sync.aligned.m8n8.x4.trans.shared.b16 {%0,%1,%2,%3}, [%4];"
        : "=r"(r[0]), "=r"(r[1]), "=r"(r[2]), "=r"(r[3]) : "r"(addr));
}

__device__ __forceinline__ uint32_t packh2(float lo, float hi) {
    __half2 h = __floats2half2_rn(lo, hi);
    return *(uint32_t*)&h;
}

__device__ __forceinline__ float ex2f(float x) {
    float r;
    asm("ex2.approx.f32 %0, %1;" : "=f"(r) : "f"(x));
    return r;
}

// ---------------------------------------------------------------------------
// fp32 -> fp16 conversion pass over x + 4 weights. 8 floats per thread.
// ---------------------------------------------------------------------------
__global__ __launch_bounds__(256) void tohalf_kernel(
    const float* __restrict__ x,
    const float* __restrict__ wq, const float* __restrict__ wk,
    const float* __restrict__ wv, const float* __restrict__ wo,
    __half* __restrict__ xr,
    __half* __restrict__ wqr, __half* __restrict__ wkr,
    __half* __restrict__ wvr, __half* __restrict__ wor)
{
    const int bidx = blockIdx.x;
    const float* src;
    __half* dst;
    int off;
    if (bidx < 2048) { src = x; dst = xr; off = bidx; }
    else {
        const int i = (bidx - 2048) >> 9;
        off = (bidx - 2048) & 511;
        src = (i == 0) ? wq : (i == 1) ? wk : (i == 2) ? wv : wo;
        dst = (i == 0) ? wqr : (i == 1) ? wkr : (i == 2) ? wvr : wor;
    }
    const int base = off * 2048 + threadIdx.x * 8;
    float4 v0 = *(const float4*)(src + base);
    float4 v1 = *(const float4*)(src + base + 4);
    uint4 o;
    o.x = packh2(v0.x, v0.y); o.y = packh2(v0.z, v0.w);
    o.z = packh2(v1.x, v1.y); o.w = packh2(v1.z, v1.w);
    *(uint4*)(dst + base) = o;
}

// ---------------------------------------------------------------------------
// fp16 mma.sync GEMM (unchanged from round 16): tile 256x128, warp 64x64.
// K-chunk 128 halfs as two 128B-row swizzled panels; 2 stages = 192KB.
// ---------------------------------------------------------------------------
#define GTM 256
#define GTN 128
#define GCHUNK 128
#define A_PANEL_H (GTM * 64)                  // 16384 halfs = 32KB
#define B_PANEL_H (GTN * 64)                  // 8192 halfs = 16KB
#define A_STG_H (2 * A_PANEL_H)               // 64KB
#define B_STG_H (2 * B_PANEL_H)               // 32KB
#define STG_H   (A_STG_H + B_STG_H)           // 49152 halfs = 96KB
#define GSTAGES 2
#define GEMM_SMEM (GSTAGES * STG_H * 2)       // 196608 B

__global__ __launch_bounds__(256, 1) void gemm_f16_kernel(
    const __half* __restrict__ A,
    const __half* __restrict__ W0, const __half* __restrict__ W1, const __half* __restrict__ W2,
    __half* __restrict__ C0, __half* __restrict__ C1, __half* __restrict__ C2,
    float* __restrict__ CF, int scatter)
{
    const __half* __restrict__ W = (blockIdx.z == 0) ? W0 : (blockIdx.z == 1) ? W1 : W2;
    __half* __restrict__ C       = (blockIdx.z == 0) ? C0 : (blockIdx.z == 1) ? C1 : C2;

    extern __shared__ __half smh[];

    const int tid  = threadIdx.x;
    const int wid  = tid >> 5;
    const int lane = tid & 31;
    const int g    = lane >> 2;
    const int t    = lane & 3;
    const int wm   = wid & 3;
    const int wn   = wid >> 2;
    const int nBase = blockIdx.x * GTN;
    const int mBase = blockIdx.y * GTM;

    float acc[4][8][4];
#pragma unroll
    for (int i = 0; i < 4; i++)
#pragma unroll
        for (int j = 0; j < 8; j++)
#pragma unroll
            for (int l = 0; l < 4; l++) acc[i][j][l] = 0.0f;

    const uint32_t smemA0 = smem_u32(smh);

    const int rowA = wm * 64 + (lane & 15);
    const int rowB = wn * 64 + (lane & 7) + ((lane >> 4) << 3);
    const int c4bitA = lane >> 4;
    const int c4bitB = (lane >> 3) & 1;
    const int lxor   = lane & 7;

    auto issue = [&](int c, int s) {
        const uint32_t st = smemA0 + (uint32_t)(s * STG_H) * 2u;
#pragma unroll
        for (int i = 0; i < 16; i++) {
            const int idx = tid + 256 * i;
            const int r = idx >> 4, cg = idx & 15;
            const int pan = cg >> 3, c8 = cg & 7;
            const uint32_t off =
                (uint32_t)(pan * A_PANEL_H * 2 + r * 128 + (((c8 ^ (r & 7)) & 7) << 4));
            cp_async16(st + off, A + (size_t)(mBase + r) * DMODEL + c * GCHUNK + cg * 8);
        }
#pragma unroll
        for (int i = 0; i < 8; i++) {
            const int idx = tid + 256 * i;
            const int r = idx >> 4, cg = idx & 15;
            const int pan = cg >> 3, c8 = cg & 7;
            const uint32_t off =
                (uint32_t)(pan * B_PANEL_H * 2 + r * 128 + (((c8 ^ (r & 7)) & 7) << 4));
            cp_async16(st + (uint32_t)A_STG_H * 2u + off,
                       W + (size_t)(nBase + r) * DMODEL + c * GCHUNK + cg * 8);
        }
    };

    issue(0, 0); CP_COMMIT();

    const int NCHUNK = DMODEL / GCHUNK;   // 8
    for (int c = 0; c < NCHUNK; c++) {
        CP_WAIT(0);
        __syncthreads();
        if (c + 1 < NCHUNK) issue(c + 1, (c + 1) & 1);
        CP_COMMIT();

        const uint32_t Ast = smemA0 + (uint32_t)((c & 1) * STG_H) * 2u;
        const uint32_t Bst = Ast + (uint32_t)A_STG_H * 2u;

#pragma unroll
        for (int ks = 0; ks < 8; ks++) {
            const uint32_t panA = (uint32_t)((ks >> 2) * A_PANEL_H) * 2u;
            const uint32_t panB = (uint32_t)((ks >> 2) * B_PANEL_H) * 2u;
            const int k2 = ks & 3;
            const int xa = ((2 * k2 + c4bitA) ^ lxor) & 7;
            const int xb = ((2 * k2 + c4bitB) ^ lxor) & 7;

            uint32_t a[4][4];
#pragma unroll
            for (int mt = 0; mt < 4; mt++)
                ldsm4(a[mt], Ast + panA + (uint32_t)((rowA + mt * 16) * 128 + xa * 16));

            uint32_t b[4][4];
#pragma unroll
            for (int ntp = 0; ntp < 4; ntp++)
                ldsm4(b[ntp], Bst + panB + (uint32_t)((rowB + ntp * 16) * 128 + xb * 16));

#pragma unroll
            for (int mt = 0; mt < 4; mt++)
#pragma unroll
                for (int ntp = 0; ntp < 4; ntp++) {
                    mma_f16(acc[mt][2 * ntp],     a[mt][0], a[mt][1], a[mt][2], a[mt][3],
                            b[ntp][0], b[ntp][1]);
                    mma_f16(acc[mt][2 * ntp + 1], a[mt][0], a[mt][1], a[mt][2], a[mt][3],
                            b[ntp][2], b[ntp][3]);
                }
        }
    }

    const float qs = (scatter && blockIdx.z == 0) ? QSCALE : 1.0f;
#pragma unroll
    for (int mt = 0; mt < 4; mt++) {
#pragma unroll
        for (int half = 0; half < 2; half++) {
            const int m = mBase + wm * 64 + mt * 16 + g + half * 8;
#pragma unroll
            for (int nt = 0; nt < 8; nt++) {
                const int n = nBase + wn * 64 + nt * 8 + 2 * t;
                const float vx = acc[mt][nt][half * 2 + 0];
                const float vy = acc[mt][nt][half * 2 + 1];
                if (scatter) {
                    const int b = m >> 11, s = m & 2047;
                    const int head = n >> 6, d0 = n & 63;
                    const uint32_t u = packh2(vx * qs, vy * qs);
                    *(uint32_t*)&C[(((size_t)((b << 4) + head) * S_LEN + s) * DK + d0)] = u;
                } else {
                    float2 v; v.x = vx; v.y = vy;
                    *(float2*)&CF[(size_t)m * DMODEL + n] = v;
                }
            }
        }
    }
}

// ---------------------------------------------------------------------------
// fp16 flash attention, 2 CTAs/SM. CTA: 256 thr (8 warps), Q block 128 rows
// (16 rows = ONE m-tile per warp -> s_/o_ halve -> <=128 regs).
// kv tile 64, 2-stage cp.async. Q/K frags via ldmatrix on padded 144B rows;
// exp2-domain softmax; P in registers; V via ldmatrix.x4.trans.
// smem 55.3KB/CTA -> 2 CTAs/SM = 4 warps/SMSP (latency hiding for the
// QK->softmax->PV serial chain).
// ---------------------------------------------------------------------------
#define AKSTR   72                        // halfs per row (144B)
#define K_TILE_H (64 * AKSTR)             // 4608 halfs
#define ASTG_H  (2 * K_TILE_H)            // 9216 halfs (K then V)
#define SQ_OFF_H (2 * ASTG_H)             // 18432 halfs
#define SQW_H   (16 * AKSTR)              // 1152 halfs per warp
#define ATTN_SMEM ((SQ_OFF_H + 8 * SQW_H) * 2)   // 55296 B

__global__ __launch_bounds__(256, 2) void attn_f16_kernel(
    const __half* __restrict__ Q, const __half* __restrict__ K,
    const __half* __restrict__ V, __half* __restrict__ Oatt)
{
    extern __shared__ __half smh[];

    const int tid  = threadIdx.x;
    const int wid  = tid >> 5;
    const int lane = tid & 31;
    const int g    = lane >> 2;
    const int t    = lane & 3;
    const int qb   = blockIdx.x;            // 0..15 (128 rows each)
    const int bh   = blockIdx.y;            // 0..31
    const int b    = bh >> 4;
    const int h    = bh & 15;

    const uint32_t smemB = smem_u32(smh);
    const uint32_t sqwB  = smemB + (uint32_t)(SQ_OFF_H + wid * SQW_H) * 2u;
    __half* sQw = smh + SQ_OFF_H + wid * SQW_H;

    // ---- Stage Q slice (16 rows/warp) into padded rows (already scaled)
    {
        const __half* Qg = Q + ((size_t)bh * S_LEN + qb * 128 + wid * 16) * DK;
#pragma unroll
        for (int i = 0; i < 4; i++) {
            const int idx = lane + 32 * i;      // 16 rows x 8 groups = 128
            const int r = idx >> 3, cg = idx & 7;
            *(uint4*)(sQw + r * AKSTR + cg * 8) = *(const uint4*)(Qg + r * DK + cg * 8);
        }
        __syncwarp();
    }

    float o_[8][4];
#pragma unroll
    for (int nt = 0; nt < 8; nt++)
#pragma unroll
        for (int l = 0; l < 4; l++) o_[nt][l] = 0.0f;
    float mrow0 = -1e30f, mrow1 = -1e30f;
    float lrow0 = 0.0f, lrow1 = 0.0f;

    const __half* Kg = K + (size_t)bh * S_LEN * DK;
    const __half* Vg = V + (size_t)bh * S_LEN * DK;

    // 64-row K/V tile loader: 512 K-groups + 512 V-groups, 2+2 per thread
    auto issue = [&](int kv, int st) {
        const uint32_t stb = smemB + (uint32_t)(st * ASTG_H) * 2u;
        const __half* kS = Kg + (size_t)kv * 64 * DK;
        const __half* vS = Vg + (size_t)kv * 64 * DK;
#pragma unroll
        for (int i = 0; i < 2; i++) {
            const int idx = tid + 256 * i;      // 0..511
            const int r = idx >> 3, cg = idx & 7;
            cp_async16(stb + (uint32_t)(r * 144 + cg * 16), kS + r * DK + cg * 8);
            cp_async16(stb + (uint32_t)K_TILE_H * 2u + (uint32_t)(r * 144 + cg * 16),
                       vS + r * DK + cg * 8);
        }
    };

    issue(0, 0); CP_COMMIT();

    // ldmatrix lane bases
    const uint32_t qoff = (uint32_t)((lane & 15) * 144 + ((lane >> 4) << 4));
    const uint32_t koff = (uint32_t)(((lane & 7) + ((lane >> 4) << 3)) * 144
                                     + (((lane >> 3) & 1) << 4));

    const int NKV = S_LEN / 64;   // 32
    for (int kv = 0; kv < NKV; kv++) {
        CP_WAIT(0);
        __syncthreads();
        if (kv + 1 < NKV) issue(kv + 1, (kv + 1) & 1);
        CP_COMMIT();

        const uint32_t Kst = smemB + (uint32_t)((kv & 1) * ASTG_H) * 2u;
        const uint32_t Vbase = Kst + (uint32_t)K_TILE_H * 2u;

        // ---- scores S = Q' K^T (log2 domain), 16x64/warp
        float s_[8][4];
#pragma unroll
        for (int nt = 0; nt < 8; nt++)
#pragma unroll
            for (int l = 0; l < 4; l++) s_[nt][l] = 0.0f;

#pragma unroll
        for (int ks = 0; ks < 4; ks++) {
            uint32_t a[4];
            ldsm4(a, sqwB + qoff + (uint32_t)(ks * 32));
            uint32_t bb[4][4];
#pragma unroll
            for (int ntp = 0; ntp < 4; ntp++)
                ldsm4(bb[ntp], Kst + koff + (uint32_t)(ntp * 16 * 144 + ks * 32));
#pragma unroll
            for (int ntp = 0; ntp < 4; ntp++) {
                mma_f16(s_[2 * ntp],     a[0], a[1], a[2], a[3], bb[ntp][0], bb[ntp][1]);
                mma_f16(s_[2 * ntp + 1], a[0], a[1], a[2], a[3], bb[ntp][2], bb[ntp][3]);
            }
        }

        // ---- online softmax (exp2 domain, fp32)
        {
            float mx0 = -1e30f, mx1 = -1e30f;
#pragma unroll
            for (int nt = 0; nt < 8; nt++) {
                mx0 = fmaxf(mx0, fmaxf(s_[nt][0], s_[nt][1]));
                mx1 = fmaxf(mx1, fmaxf(s_[nt][2], s_[nt][3]));
            }
            mx0 = fmaxf(mx0, __shfl_xor_sync(0xffffffffu, mx0, 1));
            mx0 = fmaxf(mx0, __shfl_xor_sync(0xffffffffu, mx0, 2));
            mx1 = fmaxf(mx1, __shfl_xor_sync(0xffffffffu, mx1, 1));
            mx1 = fmaxf(mx1, __shfl_xor_sync(0xffffffffu, mx1, 2));

            float mn0 = fmaxf(mrow0, mx0), mn1 = fmaxf(mrow1, mx1);
            float al0 = ex2f(mrow0 - mn0), al1 = ex2f(mrow1 - mn1);
            mrow0 = mn0; mrow1 = mn1;

            float s0 = 0.0f, s1 = 0.0f;
#pragma unroll
            for (int nt = 0; nt < 8; nt++) {
                s_[nt][0] = ex2f(s_[nt][0] - mn0); s0 += s_[nt][0];
                s_[nt][1] = ex2f(s_[nt][1] - mn0); s0 += s_[nt][1];
                s_[nt][2] = ex2f(s_[nt][2] - mn1); s1 += s_[nt][2];
                s_[nt][3] = ex2f(s_[nt][3] - mn1); s1 += s_[nt][3];
            }
            s0 += __shfl_xor_sync(0xffffffffu, s0, 1);
            s0 += __shfl_xor_sync(0xffffffffu, s0, 2);
            s1 += __shfl_xor_sync(0xffffffffu, s1, 1);
            s1 += __shfl_xor_sync(0xffffffffu, s1, 2);
            lrow0 = lrow0 * al0 + s0;
            lrow1 = lrow1 * al1 + s1;

#pragma unroll
            for (int nt = 0; nt < 8; nt++) {
                o_[nt][0] *= al0; o_[nt][1] *= al0;
                o_[nt][2] *= al1; o_[nt][3] *= al1;
            }
        }

        // ---- O += P V : P packed reg->reg, V b-frags via ldmatrix.trans
#pragma unroll
        for (int kt = 0; kt < 4; kt++) {
            uint32_t ap[4];
            ap[0] = packh2(s_[2 * kt][0],     s_[2 * kt][1]);
            ap[1] = packh2(s_[2 * kt][2],     s_[2 * kt][3]);
            ap[2] = packh2(s_[2 * kt + 1][0], s_[2 * kt + 1][1]);
            ap[3] = packh2(s_[2 * kt + 1][2], s_[2 * kt + 1][3]);
            const int kvrow = kt * 16 + (lane & 15);
#pragma unroll
            for (int ntp = 0; ntp < 4; ntp++) {
                const int colb = ntp * 16 + ((lane >> 4) << 3);
                uint32_t vv[4];
                ldsm4t(vv, Vbase + (uint32_t)(kvrow * 144 + colb * 2));
                mma_f16(o_[2 * ntp],     ap[0], ap[1], ap[2], ap[3], vv[0], vv[1]);
                mma_f16(o_[2 * ntp + 1], ap[0], ap[1], ap[2], ap[3], vv[2], vv[3]);
            }
        }
    }

    // ---- epilogue: normalize, write fp16 (B,S,D)
    {
        const float inv0 = 1.0f / lrow0, inv1 = 1.0f / lrow1;
        const int row0 = qb * 128 + wid * 16 + g;
#pragma unroll
        for (int nt = 0; nt < 8; nt++) {
            const int col = h * DK + nt * 8 + 2 * t;
            const uint32_t u0 = packh2(o_[nt][0] * inv0, o_[nt][1] * inv0);
            const uint32_t u1 = packh2(o_[nt][2] * inv1, o_[nt][3] * inv1);
            *(uint32_t*)&Oatt[((size_t)b * S_LEN + row0) * DMODEL + col]     = u0;
            *(uint32_t*)&Oatt[((size_t)b * S_LEN + row0 + 8) * DMODEL + col] = u1;
        }
    }
}

// ---------------------------------------------------------------------------
extern "C" void kernel_launch(void* const* d_in, const int* in_sizes, int n_in,
                              void* d_out, int out_size)
{
    const float* x  = (const float*)d_in[0];
    const float* Wq = (const float*)d_in[1];
    const float* Wk = (const float*)d_in[2];
    const float* Wv = (const float*)d_in[3];
    const float* Wo = (const float*)d_in[4];
    float* out = (float*)d_out;

    __half *qp, *kp, *vp, *attp, *hp;
    cudaGetSymbolAddress((void**)&qp,   g_q);
    cudaGetSymbolAddress((void**)&kp,   g_k);
    cudaGetSymbolAddress((void**)&vp,   g_v);
    cudaGetSymbolAddress((void**)&attp, g_att);
    cudaGetSymbolAddress((void**)&hp,   g_half);

    __half* xr  = hp;
    __half* wqr = hp + 4 * 1024 * 1024;
    __half* wkr = hp + 5 * 1024 * 1024;
    __half* wvr = hp + 6 * 1024 * 1024;
    __half* wor = hp + 7 * 1024 * 1024;

    // 0) fp32 -> fp16 conversion of all GEMM operands
    tohalf_kernel<<<4096, 256>>>(x, Wq, Wk, Wv, Wo, xr, wqr, wkr, wvr, wor);

    cudaFuncSetAttribute(gemm_f16_kernel, cudaFuncAttributeMaxDynamicSharedMemorySize,
                         GEMM_SMEM);
    cudaFuncSetAttribute(attn_f16_kernel, cudaFuncAttributeMaxDynamicSharedMemorySize,
                         ATTN_SMEM);

    // 1) Fused QKV projections (fp16 mma), scatter to (B,H,S,dk); Q pre-scaled
    dim3 gQKV(DMODEL / GTN, M_TOTAL / GTM, 3);
    gemm_f16_kernel<<<gQKV, 256, GEMM_SMEM>>>(xr, wqr, wkr, wvr, qp, kp, vp,
                                              nullptr, 1);

    // 2) Flash attention (fp16 mma, exp2 softmax, 2 CTAs/SM) -> (B,S,D) fp16
    dim3 gA(S_LEN / 128, BATCH * NHEADS);
    attn_f16_kernel<<<gA, 256, ATTN_SMEM>>>(qp, kp, vp, attp);

    // 3) Output projection (fp16 mma) -> fp32 d_out
    dim3 gO(DMODEL / GTN, M_TOTAL / GTM, 1);
    gemm_f16_kernel<<<gO, 256, GEMM_SMEM>>>(attp, wor, wor, wor,
                                            nullptr, nullptr, nullptr, out, 0);
}